// round 1
// baseline (speedup 1.0000x reference)
#include <cuda_runtime.h>

// Problem constants (match reference setup_inputs)
#define NN      50000
#define EE      800000
#define INDIM   128
#define D       64
#define H       4
#define NR      20
#define NB      8
#define STCOLS  160           // 80 src-score cols + 80 dst-score cols
#define WBIG_COLS 480         // 64 (z) + 256 (self) + 160 (st)
#define WBIG_STRIDE 512

// Scratch (static device arrays: no allocation allowed)
__device__ __align__(16) float g_z[NN * D];            // 12.8 MB
__device__ __align__(16) float g_st[NN * STCOLS];      // 32 MB
__device__ float g_Wst[D * STCOLS];                    // 40 KB
__device__ __align__(16) float g_Wbig[INDIM * WBIG_STRIDE];  // 256 KB

// ---------------------------------------------------------------------------
// K0a: Wst[c][jj] : per-relation attention weights after basis combination,
// split into src-part (jj<80: rows 0..63 of attn_fcs) and dst-part (jj>=80).
// jj = r*4 + h (+80 for dst part)
// ---------------------------------------------------------------------------
__global__ void build_wst_kernel(const float* __restrict__ w_comp,
                                 const float* __restrict__ aw) {
    int idx = blockIdx.x * blockDim.x + threadIdx.x;
    if (idx >= D * STCOLS) return;
    int c  = idx / STCOLS;
    int jj = idx % STCOLS;
    int r, hh, cc;
    if (jj < 80) { r = jj >> 2; hh = jj & 3; cc = c; }
    else         { int j2 = jj - 80; r = j2 >> 2; hh = j2 & 3; cc = c + D; }
    float acc = 0.f;
#pragma unroll
    for (int b = 0; b < NB; b++)
        acc += w_comp[r * NB + b] * aw[b * (2 * D * H) + cc * H + hh];
    g_Wst[idx] = acc;
}

// ---------------------------------------------------------------------------
// K0b: Wbig[k][j], k in [0,128), j in [0,480):
//   j <  64 : fc_w^T                      (z = h @ fc_w^T)
//   j < 320 : self_fc_w^T                 (self term, goes straight to d_out)
//   j < 480 : fc_w^T @ Wst                (st = z @ Wst = h @ (fc_w^T @ Wst))
// ---------------------------------------------------------------------------
__global__ void build_wbig_kernel(const float* __restrict__ fc_w,
                                  const float* __restrict__ self_fc_w) {
    int idx = blockIdx.x * blockDim.x + threadIdx.x;
    if (idx >= INDIM * WBIG_COLS) return;
    int k = idx / WBIG_COLS;
    int j = idx % WBIG_COLS;
    float val;
    if (j < D) {
        val = fc_w[j * INDIM + k];
    } else if (j < D + H * D) {
        val = self_fc_w[(j - D) * INDIM + k];
    } else {
        int jj = j - (D + H * D);
        float acc = 0.f;
#pragma unroll 8
        for (int c = 0; c < D; c++)
            acc += fc_w[c * INDIM + k] * g_Wst[c * STCOLS + jj];
        val = acc;
    }
    g_Wbig[k * WBIG_STRIDE + j] = val;
}

// ---------------------------------------------------------------------------
// K1: SGEMM  C[N,480] = h[N,128] @ Wbig[128,480]
// 64x64 block tile, BK=16, 256 threads, 4x4 per-thread microtile.
// Output routed: cols [0,64)->g_z, [64,320)->d_out, [320,480)->g_st
// ---------------------------------------------------------------------------
#define BM 64
#define BN 64
#define BK 16

__global__ __launch_bounds__(256) void gemm_kernel(const float* __restrict__ A,
                                                   float* __restrict__ out) {
    __shared__ float As[BK][BM + 4];   // transposed A tile (k-major)
    __shared__ float Bs[BK][BN];

    const int tid = threadIdx.x;
    const int tx = tid & 15;           // 16 col groups
    const int ty = tid >> 4;           // 16 row groups
    const int rowBase = blockIdx.y * BM;
    const int colBase = blockIdx.x * BN;

    // A tile load mapping: 64 rows x 16 k, float4 along k
    const int aRow = tid >> 2;
    const int aK   = (tid & 3) << 2;
    // B tile load mapping: 16 k x 64 cols, float4 along cols
    const int bK   = tid >> 4;
    const int bCol = (tid & 15) << 2;

    float acc[4][4];
#pragma unroll
    for (int i = 0; i < 4; i++)
#pragma unroll
        for (int j = 0; j < 4; j++) acc[i][j] = 0.f;

    for (int k0 = 0; k0 < INDIM; k0 += BK) {
        // load A (row-guarded)
        float4 av = make_float4(0.f, 0.f, 0.f, 0.f);
        int gr = rowBase + aRow;
        if (gr < NN)
            av = *reinterpret_cast<const float4*>(A + (size_t)gr * INDIM + k0 + aK);
        As[aK + 0][aRow] = av.x;
        As[aK + 1][aRow] = av.y;
        As[aK + 2][aRow] = av.z;
        As[aK + 3][aRow] = av.w;
        // load B (stride 512; cols >=480 are unused garbage, never stored)
        float4 bv = *reinterpret_cast<const float4*>(
            g_Wbig + (size_t)(k0 + bK) * WBIG_STRIDE + colBase + bCol);
        *reinterpret_cast<float4*>(&Bs[bK][bCol]) = bv;
        __syncthreads();

#pragma unroll
        for (int kk = 0; kk < BK; kk++) {
            float4 a4 = *reinterpret_cast<const float4*>(&As[kk][ty * 4]);
            float4 b4 = *reinterpret_cast<const float4*>(&Bs[kk][tx * 4]);
            float ar[4] = {a4.x, a4.y, a4.z, a4.w};
            float br[4] = {b4.x, b4.y, b4.z, b4.w};
#pragma unroll
            for (int i = 0; i < 4; i++)
#pragma unroll
                for (int j = 0; j < 4; j++) acc[i][j] += ar[i] * br[j];
        }
        __syncthreads();
    }

    // routed store
#pragma unroll
    for (int i = 0; i < 4; i++) {
        int row = rowBase + ty * 4 + i;
        if (row >= NN) continue;
#pragma unroll
        for (int j = 0; j < 4; j++) {
            int col = colBase + tx * 4 + j;
            float v = acc[i][j];
            if (col < D) {
                g_z[row * D + col] = v;
            } else if (col < D + H * D) {
                out[(size_t)row * (H * D) + (col - D)] = v;
            } else if (col < WBIG_COLS) {
                g_st[row * STCOLS + (col - (D + H * D))] = v;
            }
        }
    }
}

// ---------------------------------------------------------------------------
// K2: edge kernel. 64 threads per edge: thread t handles head h = t/16 and
// feature block d0 = (t%16)*4.  a = leaky_relu(s[src,r,h] + t[dst,r,h]);
// red.global.add.v4.f32 of a * z[src, d0..d0+3] into d_out[dst, h*64+d0].
// ---------------------------------------------------------------------------
__global__ __launch_bounds__(256) void edge_kernel(const int* __restrict__ src,
                                                   const int* __restrict__ dst,
                                                   const int* __restrict__ rel,
                                                   float* __restrict__ out) {
    int tid = blockIdx.x * blockDim.x + threadIdx.x;
    int e = tid >> 6;
    if (e >= EE) return;
    int t  = tid & 63;
    int hh = t >> 4;
    int d0 = (t & 15) << 2;

    int s = __ldg(&src[e]);
    int dd = __ldg(&dst[e]);
    int r = __ldg(&rel[e]);

    float sv = __ldg(&g_st[s * STCOLS + r * 4 + hh]);
    float tv = __ldg(&g_st[dd * STCOLS + 80 + r * 4 + hh]);
    float a = sv + tv;
    a = (a > 0.f) ? a : 0.01f * a;

    float4 zv = *reinterpret_cast<const float4*>(g_z + s * D + d0);
    float mx = a * zv.x, my = a * zv.y, mz = a * zv.z, mw = a * zv.w;

    float* p = out + (size_t)dd * (H * D) + hh * D + d0;
    asm volatile("red.global.add.v4.f32 [%0], {%1,%2,%3,%4};"
                 :: "l"(p), "f"(mx), "f"(my), "f"(mz), "f"(mw)
                 : "memory");
}

// ---------------------------------------------------------------------------
// launch
// ---------------------------------------------------------------------------
extern "C" void kernel_launch(void* const* d_in, const int* in_sizes, int n_in,
                              void* d_out, int out_size) {
    const float* h_in       = (const float*)d_in[0];
    const float* fc_w       = (const float*)d_in[1];
    const float* self_fc_w  = (const float*)d_in[2];
    const float* attn_w     = (const float*)d_in[3];
    const float* w_comp     = (const float*)d_in[4];
    const int*   src        = (const int*)d_in[5];
    const int*   dst        = (const int*)d_in[6];
    const int*   rel        = (const int*)d_in[7];
    float* out = (float*)d_out;

    build_wst_kernel<<<(D * STCOLS + 255) / 256, 256>>>(w_comp, attn_w);
    build_wbig_kernel<<<(INDIM * WBIG_COLS + 255) / 256, 256>>>(fc_w, self_fc_w);

    dim3 ggrid(WBIG_STRIDE / BN, (NN + BM - 1) / BM);   // 8 x 782
    gemm_kernel<<<ggrid, 256>>>(h_in, out);

    int edge_threads = EE * 64;
    edge_kernel<<<(edge_threads + 255) / 256, 256>>>(src, dst, rel, out);
}

// round 4
// speedup vs baseline: 1.2798x; 1.2798x over previous
#include <cuda_runtime.h>

#define NN      50000
#define EE      800000
#define INDIM   128
#define D       64
#define H       4
#define NR      20
#define NB      8
#define STCOLS  160
#define W1COLS  320          // 64 (z) + 256 (self)
#define WSTLD   192          // Wst stride (160 cols padded to 3x64)

// ---- static scratch (no allocation allowed) ----
__device__ __align__(16) float g_z[NN * D];              // 12.8 MB
__device__ __align__(16) float g_st[NN * STCOLS];        // 32 MB
__device__ __align__(16) float g_W1[INDIM * W1COLS];     // 160 KB
__device__ __align__(16) float g_Wst[D * WSTLD];         // 48 KB
__device__ int g_deg[NN];
__device__ int g_rowptr[NN + 1];
__device__ int g_cursor[NN];
__device__ unsigned g_csr[EE];

// ---------------------------------------------------------------------------
// Wst[c][jj]: basis-combined attention weights. jj = r*4+h for src part
// (rows 0..63 of attn_fcs), jj-80 = r*4+h for dst part (rows 64..127).
// Padded cols [160,192) zeroed.
// ---------------------------------------------------------------------------
__global__ void build_wst_kernel(const float* __restrict__ w_comp,
                                 const float* __restrict__ aw) {
    int idx = blockIdx.x * blockDim.x + threadIdx.x;
    if (idx >= D * WSTLD) return;
    int c  = idx / WSTLD;
    int jj = idx % WSTLD;
    if (jj >= STCOLS) { g_Wst[idx] = 0.f; return; }
    int r, hh, cc;
    if (jj < 80) { r = jj >> 2; hh = jj & 3; cc = c; }
    else         { int j2 = jj - 80; r = j2 >> 2; hh = j2 & 3; cc = c + D; }
    float acc = 0.f;
#pragma unroll
    for (int b = 0; b < NB; b++)
        acc += w_comp[r * NB + b] * aw[b * (2 * D * H) + cc * H + hh];
    g_Wst[idx] = acc;
}

// W1[k][j]: j<64 -> fc_w^T ; j in [64,320) -> self_fc_w^T
__global__ void build_w1_kernel(const float* __restrict__ fc_w,
                                const float* __restrict__ self_fc_w) {
    int idx = blockIdx.x * blockDim.x + threadIdx.x;
    if (idx >= INDIM * W1COLS) return;
    int k = idx / W1COLS;
    int j = idx % W1COLS;
    g_W1[idx] = (j < D) ? fc_w[j * INDIM + k] : self_fc_w[(j - D) * INDIM + k];
}

// ---------------------------------------------------------------------------
// SGEMM tiles: BM=128, BN=64, BK=16, 256 threads, 8x4 microtile.
// Per k-step: 3 LDS.128 + 32 FFMA (FFMA-bound).
// ---------------------------------------------------------------------------
#define BM 128
#define BN 64
#define BK 16

// GEMM1: C[N,320] = h[N,128] @ W1[128,320]; cols [0,64)->g_z, rest->d_out
__global__ __launch_bounds__(256) void gemm1_kernel(const float* __restrict__ A,
                                                    float* __restrict__ out) {
    __shared__ float As[BK][BM + 4];
    __shared__ float Bs[BK][BN];
    const int tid = threadIdx.x;
    const int tx = tid & 15;           // col group (4 cols)
    const int ty = tid >> 4;           // row group (8 rows)
    const int rowBase = blockIdx.y * BM;
    const int colBase = blockIdx.x * BN;
    const int aRow = tid >> 1;               // 0..127
    const int aK   = (tid & 1) << 3;         // 0 or 8
    const int bK   = tid >> 4;               // 0..15
    const int bCol = (tid & 15) << 2;        // 0..60

    float acc[8][4];
#pragma unroll
    for (int i = 0; i < 8; i++)
#pragma unroll
        for (int j = 0; j < 4; j++) acc[i][j] = 0.f;

    for (int k0 = 0; k0 < INDIM; k0 += BK) {
        int gr = rowBase + aRow;
        float4 av0 = make_float4(0.f, 0.f, 0.f, 0.f);
        float4 av1 = make_float4(0.f, 0.f, 0.f, 0.f);
        if (gr < NN) {
            const float* ap = A + (size_t)gr * INDIM + k0 + aK;
            av0 = *reinterpret_cast<const float4*>(ap);
            av1 = *reinterpret_cast<const float4*>(ap + 4);
        }
        As[aK + 0][aRow] = av0.x; As[aK + 1][aRow] = av0.y;
        As[aK + 2][aRow] = av0.z; As[aK + 3][aRow] = av0.w;
        As[aK + 4][aRow] = av1.x; As[aK + 5][aRow] = av1.y;
        As[aK + 6][aRow] = av1.z; As[aK + 7][aRow] = av1.w;
        *reinterpret_cast<float4*>(&Bs[bK][bCol]) =
            *reinterpret_cast<const float4*>(g_W1 + (size_t)(k0 + bK) * W1COLS + colBase + bCol);
        __syncthreads();

#pragma unroll
        for (int kk = 0; kk < BK; kk++) {
            float4 a0 = *reinterpret_cast<const float4*>(&As[kk][ty * 8]);
            float4 a1 = *reinterpret_cast<const float4*>(&As[kk][ty * 8 + 4]);
            float4 b4 = *reinterpret_cast<const float4*>(&Bs[kk][tx * 4]);
            float ar[8] = {a0.x, a0.y, a0.z, a0.w, a1.x, a1.y, a1.z, a1.w};
            float br[4] = {b4.x, b4.y, b4.z, b4.w};
#pragma unroll
            for (int i = 0; i < 8; i++)
#pragma unroll
                for (int j = 0; j < 4; j++) acc[i][j] += ar[i] * br[j];
        }
        __syncthreads();
    }

#pragma unroll
    for (int i = 0; i < 8; i++) {
        int row = rowBase + ty * 8 + i;
        if (row >= NN) continue;
#pragma unroll
        for (int j = 0; j < 4; j++) {
            int col = colBase + tx * 4 + j;
            float v = acc[i][j];
            if (col < D) g_z[row * D + col] = v;
            else         out[(size_t)row * (H * D) + (col - D)] = v;
        }
    }
}

// GEMM2: st[N,160] = z[N,64] @ Wst[64,192(pad)]
__global__ __launch_bounds__(256) void gemm2_kernel() {
    __shared__ float As[BK][BM + 4];
    __shared__ float Bs[BK][BN];
    const int tid = threadIdx.x;
    const int tx = tid & 15, ty = tid >> 4;
    const int rowBase = blockIdx.y * BM;
    const int colBase = blockIdx.x * BN;
    const int aRow = tid >> 1;
    const int aK   = (tid & 1) << 3;
    const int bK   = tid >> 4;
    const int bCol = (tid & 15) << 2;

    float acc[8][4];
#pragma unroll
    for (int i = 0; i < 8; i++)
#pragma unroll
        for (int j = 0; j < 4; j++) acc[i][j] = 0.f;

    for (int k0 = 0; k0 < D; k0 += BK) {
        int gr = rowBase + aRow;
        float4 av0 = make_float4(0.f, 0.f, 0.f, 0.f);
        float4 av1 = make_float4(0.f, 0.f, 0.f, 0.f);
        if (gr < NN) {
            const float* ap = g_z + (size_t)gr * D + k0 + aK;
            av0 = *reinterpret_cast<const float4*>(ap);
            av1 = *reinterpret_cast<const float4*>(ap + 4);
        }
        As[aK + 0][aRow] = av0.x; As[aK + 1][aRow] = av0.y;
        As[aK + 2][aRow] = av0.z; As[aK + 3][aRow] = av0.w;
        As[aK + 4][aRow] = av1.x; As[aK + 5][aRow] = av1.y;
        As[aK + 6][aRow] = av1.z; As[aK + 7][aRow] = av1.w;
        *reinterpret_cast<float4*>(&Bs[bK][bCol]) =
            *reinterpret_cast<const float4*>(g_Wst + (size_t)(k0 + bK) * WSTLD + colBase + bCol);
        __syncthreads();

#pragma unroll
        for (int kk = 0; kk < BK; kk++) {
            float4 a0 = *reinterpret_cast<const float4*>(&As[kk][ty * 8]);
            float4 a1 = *reinterpret_cast<const float4*>(&As[kk][ty * 8 + 4]);
            float4 b4 = *reinterpret_cast<const float4*>(&Bs[kk][tx * 4]);
            float ar[8] = {a0.x, a0.y, a0.z, a0.w, a1.x, a1.y, a1.z, a1.w};
            float br[4] = {b4.x, b4.y, b4.z, b4.w};
#pragma unroll
            for (int i = 0; i < 8; i++)
#pragma unroll
                for (int j = 0; j < 4; j++) acc[i][j] += ar[i] * br[j];
        }
        __syncthreads();
    }

#pragma unroll
    for (int i = 0; i < 8; i++) {
        int row = rowBase + ty * 8 + i;
        if (row >= NN) continue;
#pragma unroll
        for (int j = 0; j < 4; j++) {
            int col = colBase + tx * 4 + j;
            if (col < STCOLS) g_st[row * STCOLS + col] = acc[i][j];
        }
    }
}

// ---------------------------------------------------------------------------
// CSR build
// ---------------------------------------------------------------------------
__global__ void zero_deg_kernel() {
    int i = blockIdx.x * blockDim.x + threadIdx.x;
    if (i < NN) g_deg[i] = 0;
}

__global__ void hist_kernel(const int* __restrict__ dst) {
    int e = blockIdx.x * blockDim.x + threadIdx.x;
    if (e < EE) atomicAdd(&g_deg[dst[e]], 1);
}

#define SCAN_T 1024
#define SCAN_CHUNK 49   // 1024*49 = 50176 >= 50000
__global__ __launch_bounds__(SCAN_T) void scan_kernel() {
    __shared__ int sums[SCAN_T];
    int t = threadIdx.x;
    int beg = t * SCAN_CHUNK;
    int end = min(NN, beg + SCAN_CHUNK);
    int s = 0;
    for (int i = beg; i < end; i++) s += g_deg[i];
    sums[t] = s;
    __syncthreads();
#pragma unroll
    for (int off = 1; off < SCAN_T; off <<= 1) {
        int v = (t >= off) ? sums[t - off] : 0;
        __syncthreads();
        sums[t] += v;
        __syncthreads();
    }
    int run = (t == 0) ? 0 : sums[t - 1];
    for (int i = beg; i < end; i++) {
        g_rowptr[i] = run;
        g_cursor[i] = run;
        run += g_deg[i];
    }
    if (t == SCAN_T - 1) g_rowptr[NN] = sums[SCAN_T - 1];
}

__global__ void scatter_kernel(const int* __restrict__ src,
                               const int* __restrict__ dst,
                               const int* __restrict__ rel) {
    int e = blockIdx.x * blockDim.x + threadIdx.x;
    if (e >= EE) return;
    int d = dst[e];
    int pos = atomicAdd(&g_cursor[d], 1);
    g_csr[pos] = (unsigned)src[e] | ((unsigned)rel[e] << 16);
}

// ---------------------------------------------------------------------------
// Aggregate: one warp per destination node. 8 accumulator floats per lane
// (4 heads x 2 feature cols). Non-atomic += into d_out (self term already
// there from GEMM1).
// ---------------------------------------------------------------------------
__global__ __launch_bounds__(256) void aggregate_kernel(float* __restrict__ out) {
    int w = (blockIdx.x * blockDim.x + threadIdx.x) >> 5;
    if (w >= NN) return;
    int lane = threadIdx.x & 31;

    int beg = g_rowptr[w];
    int end = g_rowptr[w + 1];

    float acc[8];
#pragma unroll
    for (int i = 0; i < 8; i++) acc[i] = 0.f;

    const float* tvb = g_st + (size_t)w * STCOLS + 80;

    int i = beg;
    unsigned p = (i < end) ? __ldg(&g_csr[i]) : 0u;
    for (; i < end; i++) {
        unsigned pc = p;
        if (i + 1 < end) p = __ldg(&g_csr[i + 1]);
        int s = pc & 0xFFFFu;
        int r = pc >> 16;
        float4 sv = *reinterpret_cast<const float4*>(g_st + (size_t)s * STCOLS + (r << 2));
        float4 tv = *reinterpret_cast<const float4*>(tvb + (r << 2));
        float a0 = sv.x + tv.x, a1 = sv.y + tv.y, a2 = sv.z + tv.z, a3 = sv.w + tv.w;
        a0 = fmaxf(a0, 0.01f * a0);
        a1 = fmaxf(a1, 0.01f * a1);
        a2 = fmaxf(a2, 0.01f * a2);
        a3 = fmaxf(a3, 0.01f * a3);
        float2 zv = *reinterpret_cast<const float2*>(g_z + (size_t)s * D + (lane << 1));
        acc[0] += a0 * zv.x; acc[1] += a0 * zv.y;
        acc[2] += a1 * zv.x; acc[3] += a1 * zv.y;
        acc[4] += a2 * zv.x; acc[5] += a2 * zv.y;
        acc[6] += a3 * zv.x; acc[7] += a3 * zv.y;
    }

    float* o = out + (size_t)w * (H * D) + (lane << 1);
#pragma unroll
    for (int hh = 0; hh < H; hh++) {
        float2* op = reinterpret_cast<float2*>(o + hh * D);
        float2 cur = *op;
        cur.x += acc[hh * 2 + 0];
        cur.y += acc[hh * 2 + 1];
        *op = cur;
    }
}

// ---------------------------------------------------------------------------
extern "C" void kernel_launch(void* const* d_in, const int* in_sizes, int n_in,
                              void* d_out, int out_size) {
    const float* h_in      = (const float*)d_in[0];
    const float* fc_w      = (const float*)d_in[1];
    const float* self_fc_w = (const float*)d_in[2];
    const float* attn_w    = (const float*)d_in[3];
    const float* w_comp    = (const float*)d_in[4];
    const int*   src       = (const int*)d_in[5];
    const int*   dst       = (const int*)d_in[6];
    const int*   rel       = (const int*)d_in[7];
    float* out = (float*)d_out;

    // weight prep
    build_wst_kernel<<<(D * WSTLD + 255) / 256, 256>>>(w_comp, attn_w);
    build_w1_kernel<<<(INDIM * W1COLS + 255) / 256, 256>>>(fc_w, self_fc_w);

    // CSR build
    zero_deg_kernel<<<(NN + 255) / 256, 256>>>();
    hist_kernel<<<(EE + 255) / 256, 256>>>(dst);
    scan_kernel<<<1, SCAN_T>>>();
    scatter_kernel<<<(EE + 255) / 256, 256>>>(src, dst, rel);

    // node projections
    dim3 g1(W1COLS / BN, (NN + BM - 1) / BM);   // 5 x 391
    gemm1_kernel<<<g1, 256>>>(h_in, out);
    dim3 g2(WSTLD / BN, (NN + BM - 1) / BM);    // 3 x 391
    gemm2_kernel<<<g2, 256>>>();

    // edge aggregation
    aggregate_kernel<<<(NN * 32 + 255) / 256, 256>>>(out);
}

// round 7
// speedup vs baseline: 1.3753x; 1.0746x over previous
#include <cuda_runtime.h>

#define NN      50000
#define EE      800000
#define INDIM   128
#define D       64
#define H       4
#define NR      20
#define NB      8
#define STCOLS  160
#define W1COLS  320          // 64 (z) + 256 (self)
#define WSTLD   192          // Wst stride (160 cols padded to 3x64)

// ---- static scratch (no allocation allowed) ----
__device__ __align__(16) float g_z[NN * D];              // 12.8 MB
__device__ __align__(16) float g_st[NN * STCOLS];        // 32 MB
__device__ __align__(16) float g_W1[INDIM * W1COLS];     // 160 KB
__device__ __align__(16) float g_Wst[D * WSTLD];         // 48 KB
__device__ int g_deg[NN];
__device__ int g_rowptr[NN + 1];
__device__ int g_cursor[NN];
__device__ unsigned g_csr[EE];

// packed fp32x2 FMA: d = a*b + d, elementwise on 2 packed floats (Blackwell)
#define FMA_F32X2(d, a, b) \
    asm("fma.rn.f32x2 %0, %1, %2, %0;" : "+l"(d) : "l"(a), "l"(b))
#define BCAST_F32X2(d, s) \
    asm("mov.b64 %0, {%1, %1};" : "=l"(d) : "f"(s))

// ---------------------------------------------------------------------------
// Wst[c][jj]: basis-combined attention weights. jj = r*4+h for src part
// (rows 0..63 of attn_fcs), jj-80 = r*4+h for dst part (rows 64..127).
// Padded cols [160,192) zeroed.
// ---------------------------------------------------------------------------
__global__ void build_wst_kernel(const float* __restrict__ w_comp,
                                 const float* __restrict__ aw) {
    int idx = blockIdx.x * blockDim.x + threadIdx.x;
    if (idx >= D * WSTLD) return;
    int c  = idx / WSTLD;
    int jj = idx % WSTLD;
    if (jj >= STCOLS) { g_Wst[idx] = 0.f; return; }
    int r, hh, cc;
    if (jj < 80) { r = jj >> 2; hh = jj & 3; cc = c; }
    else         { int j2 = jj - 80; r = j2 >> 2; hh = j2 & 3; cc = c + D; }
    float acc = 0.f;
#pragma unroll
    for (int b = 0; b < NB; b++)
        acc += w_comp[r * NB + b] * aw[b * (2 * D * H) + cc * H + hh];
    g_Wst[idx] = acc;
}

// W1[k][j]: j<64 -> fc_w^T ; j in [64,320) -> self_fc_w^T
__global__ void build_w1_kernel(const float* __restrict__ fc_w,
                                const float* __restrict__ self_fc_w) {
    int idx = blockIdx.x * blockDim.x + threadIdx.x;
    if (idx >= INDIM * W1COLS) return;
    int k = idx / W1COLS;
    int j = idx % W1COLS;
    g_W1[idx] = (j < D) ? fc_w[j * INDIM + k] : self_fc_w[(j - D) * INDIM + k];
}

// ---------------------------------------------------------------------------
// SGEMM tiles: BM=128, BN=64, BK=16, 256 threads.
// Microtile 8x4 accumulated as 4 row-pairs x 4 cols of f32x2.
// Inner k-step: 3x LDS.128 + 4 bcast movs + 16 fma.rn.f32x2 (64 FLOP/lane).
// ---------------------------------------------------------------------------
#define BM 128
#define BN 64
#define BK 16

// GEMM1: C[N,320] = h[N,128] @ W1[128,320]; cols [0,64)->g_z, rest->d_out
__global__ __launch_bounds__(256) void gemm1_kernel(const float* __restrict__ A,
                                                    float* __restrict__ out) {
    __shared__ __align__(16) float As[BK][BM + 4];   // row stride 132 fl = 528 B (16B-mult)
    __shared__ __align__(16) float Bs[BK][BN];
    const int tid = threadIdx.x;
    const int tx = tid & 15;           // col group (4 cols)
    const int ty = tid >> 4;           // row group (8 rows)
    const int rowBase = blockIdx.y * BM;
    const int colBase = blockIdx.x * BN;
    const int aRow = tid >> 1;               // 0..127
    const int aK   = (tid & 1) << 3;         // 0 or 8
    const int bK   = tid >> 4;               // 0..15
    const int bCol = (tid & 15) << 2;        // 0..60

    unsigned long long acc2[4][4];           // [row-pair][col]
#pragma unroll
    for (int i = 0; i < 4; i++)
#pragma unroll
        for (int j = 0; j < 4; j++) acc2[i][j] = 0ull;

    for (int k0 = 0; k0 < INDIM; k0 += BK) {
        int gr = rowBase + aRow;
        float4 av0 = make_float4(0.f, 0.f, 0.f, 0.f);
        float4 av1 = make_float4(0.f, 0.f, 0.f, 0.f);
        if (gr < NN) {
            const float* ap = A + (size_t)gr * INDIM + k0 + aK;
            av0 = *reinterpret_cast<const float4*>(ap);
            av1 = *reinterpret_cast<const float4*>(ap + 4);
        }
        As[aK + 0][aRow] = av0.x; As[aK + 1][aRow] = av0.y;
        As[aK + 2][aRow] = av0.z; As[aK + 3][aRow] = av0.w;
        As[aK + 4][aRow] = av1.x; As[aK + 5][aRow] = av1.y;
        As[aK + 6][aRow] = av1.z; As[aK + 7][aRow] = av1.w;
        *reinterpret_cast<float4*>(&Bs[bK][bCol]) =
            *reinterpret_cast<const float4*>(g_W1 + (size_t)(k0 + bK) * W1COLS + colBase + bCol);
        __syncthreads();

#pragma unroll
        for (int kk = 0; kk < BK; kk++) {
            // 8 A rows as 4 packed f32x2 pairs (native layout, no packing)
            ulonglong2 A01 = *reinterpret_cast<const ulonglong2*>(&As[kk][ty * 8]);
            ulonglong2 A23 = *reinterpret_cast<const ulonglong2*>(&As[kk][ty * 8 + 4]);
            float4 b4 = *reinterpret_cast<const float4*>(&Bs[kk][tx * 4]);
            unsigned long long bb[4];
            BCAST_F32X2(bb[0], b4.x); BCAST_F32X2(bb[1], b4.y);
            BCAST_F32X2(bb[2], b4.z); BCAST_F32X2(bb[3], b4.w);
#pragma unroll
            for (int j = 0; j < 4; j++) {
                FMA_F32X2(acc2[0][j], A01.x, bb[j]);
                FMA_F32X2(acc2[1][j], A01.y, bb[j]);
                FMA_F32X2(acc2[2][j], A23.x, bb[j]);
                FMA_F32X2(acc2[3][j], A23.y, bb[j]);
            }
        }
        __syncthreads();
    }

    // store: all 4 cols of a block are on one side of the routing boundary
#pragma unroll
    for (int ip = 0; ip < 4; ip++) {
        float2 c0 = *reinterpret_cast<float2*>(&acc2[ip][0]);
        float2 c1 = *reinterpret_cast<float2*>(&acc2[ip][1]);
        float2 c2 = *reinterpret_cast<float2*>(&acc2[ip][2]);
        float2 c3 = *reinterpret_cast<float2*>(&acc2[ip][3]);
        int row0 = rowBase + ty * 8 + ip * 2;
        int col = colBase + tx * 4;
        float4 lo = make_float4(c0.x, c1.x, c2.x, c3.x);   // row0
        float4 hi = make_float4(c0.y, c1.y, c2.y, c3.y);   // row0+1
        if (col < D) {
            if (row0 < NN)     *reinterpret_cast<float4*>(g_z + (size_t)row0 * D + col) = lo;
            if (row0 + 1 < NN) *reinterpret_cast<float4*>(g_z + (size_t)(row0 + 1) * D + col) = hi;
        } else {
            int oc = col - D;
            if (row0 < NN)     *reinterpret_cast<float4*>(out + (size_t)row0 * (H * D) + oc) = lo;
            if (row0 + 1 < NN) *reinterpret_cast<float4*>(out + (size_t)(row0 + 1) * (H * D) + oc) = hi;
        }
    }
}

// GEMM2: st[N,160] = z[N,64] @ Wst[64,192(pad)]
__global__ __launch_bounds__(256) void gemm2_kernel() {
    __shared__ __align__(16) float As[BK][BM + 4];
    __shared__ __align__(16) float Bs[BK][BN];
    const int tid = threadIdx.x;
    const int tx = tid & 15, ty = tid >> 4;
    const int rowBase = blockIdx.y * BM;
    const int colBase = blockIdx.x * BN;
    const int aRow = tid >> 1;
    const int aK   = (tid & 1) << 3;
    const int bK   = tid >> 4;
    const int bCol = (tid & 15) << 2;

    unsigned long long acc2[4][4];
#pragma unroll
    for (int i = 0; i < 4; i++)
#pragma unroll
        for (int j = 0; j < 4; j++) acc2[i][j] = 0ull;

    for (int k0 = 0; k0 < D; k0 += BK) {
        int gr = rowBase + aRow;
        float4 av0 = make_float4(0.f, 0.f, 0.f, 0.f);
        float4 av1 = make_float4(0.f, 0.f, 0.f, 0.f);
        if (gr < NN) {
            const float* ap = g_z + (size_t)gr * D + k0 + aK;
            av0 = *reinterpret_cast<const float4*>(ap);
            av1 = *reinterpret_cast<const float4*>(ap + 4);
        }
        As[aK + 0][aRow] = av0.x; As[aK + 1][aRow] = av0.y;
        As[aK + 2][aRow] = av0.z; As[aK + 3][aRow] = av0.w;
        As[aK + 4][aRow] = av1.x; As[aK + 5][aRow] = av1.y;
        As[aK + 6][aRow] = av1.z; As[aK + 7][aRow] = av1.w;
        *reinterpret_cast<float4*>(&Bs[bK][bCol]) =
            *reinterpret_cast<const float4*>(g_Wst + (size_t)(k0 + bK) * WSTLD + colBase + bCol);
        __syncthreads();

#pragma unroll
        for (int kk = 0; kk < BK; kk++) {
            ulonglong2 A01 = *reinterpret_cast<const ulonglong2*>(&As[kk][ty * 8]);
            ulonglong2 A23 = *reinterpret_cast<const ulonglong2*>(&As[kk][ty * 8 + 4]);
            float4 b4 = *reinterpret_cast<const float4*>(&Bs[kk][tx * 4]);
            unsigned long long bb[4];
            BCAST_F32X2(bb[0], b4.x); BCAST_F32X2(bb[1], b4.y);
            BCAST_F32X2(bb[2], b4.z); BCAST_F32X2(bb[3], b4.w);
#pragma unroll
            for (int j = 0; j < 4; j++) {
                FMA_F32X2(acc2[0][j], A01.x, bb[j]);
                FMA_F32X2(acc2[1][j], A01.y, bb[j]);
                FMA_F32X2(acc2[2][j], A23.x, bb[j]);
                FMA_F32X2(acc2[3][j], A23.y, bb[j]);
            }
        }
        __syncthreads();
    }

#pragma unroll
    for (int ip = 0; ip < 4; ip++) {
        float2 c0 = *reinterpret_cast<float2*>(&acc2[ip][0]);
        float2 c1 = *reinterpret_cast<float2*>(&acc2[ip][1]);
        float2 c2 = *reinterpret_cast<float2*>(&acc2[ip][2]);
        float2 c3 = *reinterpret_cast<float2*>(&acc2[ip][3]);
        int row0 = rowBase + ty * 8 + ip * 2;
        int col = colBase + tx * 4;
        if (col >= STCOLS) continue;     // padded cols
        float4 lo = make_float4(c0.x, c1.x, c2.x, c3.x);
        float4 hi = make_float4(c0.y, c1.y, c2.y, c3.y);
        if (row0 < NN)     *reinterpret_cast<float4*>(g_st + (size_t)row0 * STCOLS + col) = lo;
        if (row0 + 1 < NN) *reinterpret_cast<float4*>(g_st + (size_t)(row0 + 1) * STCOLS + col) = hi;
    }
}

// ---------------------------------------------------------------------------
// CSR build
// ---------------------------------------------------------------------------
__global__ void zero_deg_kernel() {
    int i = blockIdx.x * blockDim.x + threadIdx.x;
    if (i < NN) g_deg[i] = 0;
}

__global__ void hist_kernel(const int* __restrict__ dst) {
    int t = blockIdx.x * blockDim.x + threadIdx.x;   // EE/4 threads
    if (t * 4 >= EE) return;
    int4 d4 = *reinterpret_cast<const int4*>(dst + t * 4);
    atomicAdd(&g_deg[d4.x], 1);
    atomicAdd(&g_deg[d4.y], 1);
    atomicAdd(&g_deg[d4.z], 1);
    atomicAdd(&g_deg[d4.w], 1);
}

#define SCAN_T 1024
#define SCAN_CHUNK 49   // 1024*49 = 50176 >= 50000
__global__ __launch_bounds__(SCAN_T) void scan_kernel() {
    __shared__ int sums[SCAN_T];
    int t = threadIdx.x;
    int beg = t * SCAN_CHUNK;
    int end = min(NN, beg + SCAN_CHUNK);
    int s = 0;
    for (int i = beg; i < end; i++) s += g_deg[i];
    sums[t] = s;
    __syncthreads();
#pragma unroll
    for (int off = 1; off < SCAN_T; off <<= 1) {
        int v = (t >= off) ? sums[t - off] : 0;
        __syncthreads();
        sums[t] += v;
        __syncthreads();
    }
    int run = (t == 0) ? 0 : sums[t - 1];
    for (int i = beg; i < end; i++) {
        g_rowptr[i] = run;
        g_cursor[i] = run;
        run += g_deg[i];
    }
    if (t == SCAN_T - 1) g_rowptr[NN] = sums[SCAN_T - 1];
}

__global__ void scatter_kernel(const int* __restrict__ src,
                               const int* __restrict__ dst,
                               const int* __restrict__ rel) {
    int e = blockIdx.x * blockDim.x + threadIdx.x;
    if (e >= EE) return;
    int d = dst[e];
    int pos = atomicAdd(&g_cursor[d], 1);
    g_csr[pos] = (unsigned)src[e] | ((unsigned)rel[e] << 16);
}

// ---------------------------------------------------------------------------
// Aggregate: one warp per destination node, 2-edge unrolled for MLP.
// 8 accumulator floats per lane (4 heads x 2 feature cols).
// Non-atomic += into d_out (self term already there from GEMM1).
// ---------------------------------------------------------------------------
__global__ __launch_bounds__(256) void aggregate_kernel(float* __restrict__ out) {
    int w = (blockIdx.x * blockDim.x + threadIdx.x) >> 5;
    if (w >= NN) return;
    int lane = threadIdx.x & 31;

    int beg = g_rowptr[w];
    int end = g_rowptr[w + 1];

    float acc[8];
#pragma unroll
    for (int i = 0; i < 8; i++) acc[i] = 0.f;

    const float* tvb = g_st + (size_t)w * STCOLS + 80;
    const int zoff = lane << 1;

    int i = beg;
    for (; i + 1 < end; i += 2) {
        unsigned pa = __ldg(&g_csr[i]);
        unsigned pb = __ldg(&g_csr[i + 1]);
        int sa = pa & 0xFFFFu, ra = pa >> 16;
        int sb = pb & 0xFFFFu, rb = pb >> 16;
        float4 sva = *reinterpret_cast<const float4*>(g_st + (size_t)sa * STCOLS + (ra << 2));
        float4 tva = *reinterpret_cast<const float4*>(tvb + (ra << 2));
        float4 svb = *reinterpret_cast<const float4*>(g_st + (size_t)sb * STCOLS + (rb << 2));
        float4 tvc = *reinterpret_cast<const float4*>(tvb + (rb << 2));
        float2 za = *reinterpret_cast<const float2*>(g_z + (size_t)sa * D + zoff);
        float2 zb = *reinterpret_cast<const float2*>(g_z + (size_t)sb * D + zoff);

        float a0 = sva.x + tva.x, a1 = sva.y + tva.y, a2 = sva.z + tva.z, a3 = sva.w + tva.w;
        a0 = fmaxf(a0, 0.01f * a0); a1 = fmaxf(a1, 0.01f * a1);
        a2 = fmaxf(a2, 0.01f * a2); a3 = fmaxf(a3, 0.01f * a3);
        acc[0] += a0 * za.x; acc[1] += a0 * za.y;
        acc[2] += a1 * za.x; acc[3] += a1 * za.y;
        acc[4] += a2 * za.x; acc[5] += a2 * za.y;
        acc[6] += a3 * za.x; acc[7] += a3 * za.y;

        float b0 = svb.x + tvc.x, b1 = svb.y + tvc.y, b2 = svb.z + tvc.z, b3 = svb.w + tvc.w;
        b0 = fmaxf(b0, 0.01f * b0); b1 = fmaxf(b1, 0.01f * b1);
        b2 = fmaxf(b2, 0.01f * b2); b3 = fmaxf(b3, 0.01f * b3);
        acc[0] += b0 * zb.x; acc[1] += b0 * zb.y;
        acc[2] += b1 * zb.x; acc[3] += b1 * zb.y;
        acc[4] += b2 * zb.x; acc[5] += b2 * zb.y;
        acc[6] += b3 * zb.x; acc[7] += b3 * zb.y;
    }
    if (i < end) {
        unsigned pc = __ldg(&g_csr[i]);
        int s = pc & 0xFFFFu, r = pc >> 16;
        float4 sv = *reinterpret_cast<const float4*>(g_st + (size_t)s * STCOLS + (r << 2));
        float4 tv = *reinterpret_cast<const float4*>(tvb + (r << 2));
        float a0 = sv.x + tv.x, a1 = sv.y + tv.y, a2 = sv.z + tv.z, a3 = sv.w + tv.w;
        a0 = fmaxf(a0, 0.01f * a0); a1 = fmaxf(a1, 0.01f * a1);
        a2 = fmaxf(a2, 0.01f * a2); a3 = fmaxf(a3, 0.01f * a3);
        float2 zv = *reinterpret_cast<const float2*>(g_z + (size_t)s * D + zoff);
        acc[0] += a0 * zv.x; acc[1] += a0 * zv.y;
        acc[2] += a1 * zv.x; acc[3] += a1 * zv.y;
        acc[4] += a2 * zv.x; acc[5] += a2 * zv.y;
        acc[6] += a3 * zv.x; acc[7] += a3 * zv.y;
    }

    float* o = out + (size_t)w * (H * D) + zoff;
#pragma unroll
    for (int hh = 0; hh < H; hh++) {
        float2* op = reinterpret_cast<float2*>(o + hh * D);
        float2 cur = *op;
        cur.x += acc[hh * 2 + 0];
        cur.y += acc[hh * 2 + 1];
        *op = cur;
    }
}

// ---------------------------------------------------------------------------
extern "C" void kernel_launch(void* const* d_in, const int* in_sizes, int n_in,
                              void* d_out, int out_size) {
    const float* h_in      = (const float*)d_in[0];
    const float* fc_w      = (const float*)d_in[1];
    const float* self_fc_w = (const float*)d_in[2];
    const float* attn_w    = (const float*)d_in[3];
    const float* w_comp    = (const float*)d_in[4];
    const int*   src       = (const int*)d_in[5];
    const int*   dst       = (const int*)d_in[6];
    const int*   rel       = (const int*)d_in[7];
    float* out = (float*)d_out;

    // weight prep
    build_wst_kernel<<<(D * WSTLD + 255) / 256, 256>>>(w_comp, attn_w);
    build_w1_kernel<<<(INDIM * W1COLS + 255) / 256, 256>>>(fc_w, self_fc_w);

    // CSR build
    zero_deg_kernel<<<(NN + 255) / 256, 256>>>();
    hist_kernel<<<(EE / 4 + 255) / 256, 256>>>(dst);
    scan_kernel<<<1, SCAN_T>>>();
    scatter_kernel<<<(EE + 255) / 256, 256>>>(src, dst, rel);

    // node projections
    dim3 g1(W1COLS / BN, (NN + BM - 1) / BM);   // 5 x 391
    gemm1_kernel<<<g1, 256>>>(h_in, out);
    dim3 g2(WSTLD / BN, (NN + BM - 1) / BM);    // 3 x 391
    gemm2_kernel<<<g2, 256>>>();

    // edge aggregation
    aggregate_kernel<<<(NN * 32 + 255) / 256, 256>>>(out);
}